// round 16
// baseline (speedup 1.0000x reference)
#include <cuda_runtime.h>
#include <cuda_bf16.h>
#include <cuda_fp16.h>
#include <math.h>
#include <cstdint>

#define N_NODES 50000
#define N_EDGES 800000
#define HEADS   3
#define HID     128
#define HF      (HEADS*HID)   // 384
#define NCLS    6
#define MTILES  ((N_NODES + 127) / 128)   // 391
#define CNT_BLKS 784      // count blocks in conv_a (784*1024 >= E)
#define SCT_X    131      // scatter grid columns in proj1 (131*6*1024 >= E)

// ---------------- scratch ----------------
__device__ __half g_h [(size_t)N_NODES*HF];   // projected features fp16
__device__ float g_el [2][N_NODES*HEADS];     // attention logit sets (layer1 / layer2)
__device__ float g_er [2][N_NODES*HEADS];
__device__ int   g_deg   [N_NODES];
__device__ int   g_rowptr[N_NODES + 1];
__device__ int   g_cursor[N_NODES];
__device__ int   g_csrc  [N_EDGES];

__device__ __align__(16) char g_fAh[(size_t)MTILES*32768];
__device__ __align__(16) char g_fAl[(size_t)MTILES*32768];
__device__ __align__(16) char g_fBh[(size_t)MTILES*32768];
__device__ __align__(16) char g_fBl[(size_t)MTILES*32768];
__device__ __align__(16) char g_wh [20*16384];
__device__ __align__(16) char g_wl [20*16384];

__device__ __forceinline__ uint32_t smem_u32(const void* p) {
    uint32_t a;
    asm("{ .reg .u64 t; cvta.to.shared.u64 t, %1; cvt.u32.u64 %0, t; }" : "=r"(a) : "l"(p));
    return a;
}
__device__ __forceinline__ uint32_t swz(int r, int k) {
    return (uint32_t)((r << 8) + (((((unsigned)k >> 3) & 15) ^ (r & 7)) << 4) + ((k & 7) << 1));
}
__device__ __forceinline__ void split_bf(float v, __nv_bfloat16& h, __nv_bfloat16& l) {
    h = __float2bfloat16_rn(v);
    l = __float2bfloat16_rn(v - __bfloat162float(h));
}
__device__ __forceinline__ float lrelu2(float v) { return v > 0.f ? v : 0.2f * v; }

#define CPA(dst, src) asm volatile("cp.async.cg.shared.global [%0], [%1], 16;" :: "r"(dst), "l"(src))
#define CPA_COMMIT()  asm volatile("cp.async.commit_group;")
#define LDM_X4(r0, r1, r2, r3, a) \
    asm volatile("ldmatrix.sync.aligned.m8n8.x4.shared.b16 {%0,%1,%2,%3}, [%4];" \
                 : "=r"(r0), "=r"(r1), "=r"(r2), "=r"(r3) : "r"(a))
#define MMA16816(d, a0, a1, a2, a3, b0, b1) \
    asm volatile("mma.sync.aligned.m16n8k16.row.col.f32.bf16.bf16.f32 " \
                 "{%0,%1,%2,%3}, {%4,%5,%6,%7}, {%8,%9}, {%0,%1,%2,%3};" \
                 : "+f"((d)[0]), "+f"((d)[1]), "+f"((d)[2]), "+f"((d)[3]) \
                 : "r"(a0), "r"(a1), "r"(a2), "r"(a3), "r"(b0), "r"(b1))

// ---------------- weights conversion + init zeroing ----------------
__global__ void k_conv_w(const float* W1, const float* W2, const float* l1,
                         const float* l2, const float* l3, const float* l4)
{
    int m = blockIdx.y, t = blockIdx.x;
    int flat = (blockIdx.y * gridDim.x + blockIdx.x) * 256 + threadIdx.x; // 9216 threads
    for (int i = flat; i < N_NODES; i += 9216) g_deg[i] = 0;
    for (int i = flat; i < N_NODES * HEADS; i += 9216) { g_el[0][i] = 0.f; g_er[0][i] = 0.f; }

    const float* W; int Nc, base;
    if (m == 0)      { W = W1; Nc = HF;  base = 0; }
    else if (m == 1) { W = W2; Nc = HF;  base = 6; }
    else { W = (m == 2) ? l1 : (m == 3) ? l2 : (m == 4) ? l3 : l4; Nc = HID; base = 12 + (m - 2) * 2; }
    if (t * 64 >= Nc) return;
    char* oh = g_wh + (size_t)(base + t) * 16384;
    char* ol = g_wl + (size_t)(base + t) * 16384;
    #pragma unroll
    for (int e = 0; e < 32; e++) {
        int idx = threadIdx.x + e * 256;
        int n = idx >> 7, k = idx & 127;
        float v = W[(size_t)k * Nc + t * 64 + n];
        __nv_bfloat16 h, l;
        split_bf(v, h, l);
        uint32_t o = swz(n, k);
        *(__nv_bfloat16*)(oh + o) = h;
        *(__nv_bfloat16*)(ol + o) = l;
    }
}

// ---------------- input conversion + fused degree count ----------------
__global__ void k_conv_a(const float* __restrict__ A, const int* __restrict__ dst, int M)
{
    int blk = blockIdx.x;
    if (blk >= MTILES) {
        int base = (blk - MTILES) * 1024;
        #pragma unroll
        for (int j = 0; j < 4; j++) {
            int e = base + j * 256 + threadIdx.x;
            if (e < N_EDGES) atomicAdd(&g_deg[dst[e]], 1);
        }
        return;
    }
    char* oh = g_fAh + (size_t)blk * 32768;
    char* ol = g_fAl + (size_t)blk * 32768;
    int m0 = blk * 128;
    #pragma unroll
    for (int it = 0; it < 16; it++) {
        int f = threadIdx.x + it * 256;
        int row = f >> 5, kq = (f & 31) << 2;
        float4 v = make_float4(0.f, 0.f, 0.f, 0.f);
        if (m0 + row < M) v = *(const float4*)(A + (size_t)(m0 + row) * 128 + kq);
        __nv_bfloat16 hx, hy, hz, hw, lx, ly, lz, lw;
        split_bf(v.x, hx, lx); split_bf(v.y, hy, ly);
        split_bf(v.z, hz, lz); split_bf(v.w, hw, lw);
        uint32_t o0 = swz(row, kq), o1 = swz(row, kq + 2);
        *(__nv_bfloat162*)(oh + o0) = __nv_bfloat162(hx, hy);
        *(__nv_bfloat162*)(oh + o1) = __nv_bfloat162(hz, hw);
        *(__nv_bfloat162*)(ol + o0) = __nv_bfloat162(lx, ly);
        *(__nv_bfloat162*)(ol + o1) = __nv_bfloat162(lz, lw);
    }
}

__global__ void k_scan() {
    const int T = 1024;
    const int C = (N_NODES + T - 1) / T;
    __shared__ int s[T];
    int t = threadIdx.x;
    int beg = t * C, end = min(beg + C, N_NODES);
    int sum = 0;
    for (int i = beg; i < end; i++) sum += g_deg[i];
    s[t] = sum;
    __syncthreads();
    for (int off = 1; off < T; off <<= 1) {
        int v = (t >= off) ? s[t - off] : 0;
        __syncthreads();
        s[t] += v;
        __syncthreads();
    }
    int run = (t > 0) ? s[t - 1] : 0;
    for (int i = beg; i < end; i++) {
        g_rowptr[i] = run;
        g_cursor[i] = run;
        run += g_deg[i];
    }
    if (t == T - 1) g_rowptr[N_NODES] = run;
}

// ================= projection GEMM (bf16x3, pipelined) + optional fused edge scatter =================
#define SM_AH 0
#define SM_AL 32768
#define SM_BH 65536
#define SM_BL 81920
#define SM_TOTAL 98304

__global__ void __launch_bounds__(256, 2) gemm_proj(
    const char* __restrict__ Ah, const char* __restrict__ Al, int wbase,
    const float* __restrict__ al, const float* __restrict__ ar,
    float* __restrict__ elOut, float* __restrict__ erOut,
    const int* __restrict__ src, const int* __restrict__ dst,
    __half* __restrict__ C, int M)
{
    extern __shared__ char smem[];
    const uint32_t sb = smem_u32(smem);
    int tid = threadIdx.x;

    if (blockIdx.x >= MTILES) {
        int slice = (blockIdx.x - MTILES) * 6 + blockIdx.y;
        int base = slice * 1024;
        #pragma unroll
        for (int j = 0; j < 4; j++) {
            int e = base + j * 256 + tid;
            if (e < N_EDGES) {
                int pos = atomicAdd(&g_cursor[dst[e]], 1);
                g_csrc[pos] = src[e];
            }
        }
        return;
    }

    int m0 = blockIdx.x * 128, n0 = blockIdx.y * 64;

    {
        const char* sAh = Ah + (size_t)blockIdx.x * 32768;
        const char* sAl = Al + (size_t)blockIdx.x * 32768;
        const char* sBh = g_wh + (size_t)(wbase + blockIdx.y) * 16384;
        const char* sBl = g_wl + (size_t)(wbase + blockIdx.y) * 16384;
        #pragma unroll
        for (int half = 0; half < 2; half++) {
            #pragma unroll
            for (int i = 0; i < 4; i++) {
                int idx = tid + i * 256;
                int o = (idx >> 3) * 256 + half * 128 + (idx & 7) * 16;
                CPA(sb + SM_AH + o, sAh + o);
                CPA(sb + SM_AL + o, sAl + o);
            }
            #pragma unroll
            for (int i = 0; i < 2; i++) {
                int idx = tid + i * 256;
                int o = (idx >> 3) * 256 + half * 128 + (idx & 7) * 16;
                CPA(sb + SM_BH + o, sBh + o);
                CPA(sb + SM_BL + o, sBl + o);
            }
            CPA_COMMIT();
        }
    }

    int wid = tid >> 5, lane = tid & 31;
    int wr = wid >> 1, wc = wid & 1;
    int mBase = wr * 32, nBase = wc * 32;

    float acc[2][4][4];
    #pragma unroll
    for (int i = 0; i < 2; i++)
        #pragma unroll
        for (int j = 0; j < 4; j++)
            #pragma unroll
            for (int t = 0; t < 4; t++) acc[i][j][t] = 0.f;

    int rA = (lane & 7) + ((lane >> 3) & 1) * 8;
    int kA = (lane >> 4) * 8;
    int nB = ((lane >> 4) & 1) * 8 + (lane & 7);
    int kB = ((lane >> 3) & 1) * 8;

    #pragma unroll
    for (int ph = 0; ph < 2; ph++) {
        if (ph == 0) { asm volatile("cp.async.wait_group 1;" ::: "memory"); }
        else         { asm volatile("cp.async.wait_group 0;" ::: "memory"); }
        __syncthreads();
        #pragma unroll
        for (int kk = ph * 4; kk < ph * 4 + 4; kk++) {
            int k0 = kk * 16;
            uint32_t ah[2][4], al_[2][4], bh[2][4], bl[2][4];
            #pragma unroll
            for (int mi = 0; mi < 2; mi++) {
                uint32_t off = swz(mBase + mi * 16 + rA, k0 + kA);
                LDM_X4(ah[mi][0], ah[mi][1], ah[mi][2], ah[mi][3], sb + SM_AH + off);
                LDM_X4(al_[mi][0], al_[mi][1], al_[mi][2], al_[mi][3], sb + SM_AL + off);
            }
            #pragma unroll
            for (int p = 0; p < 2; p++) {
                uint32_t off = swz(nBase + p * 16 + nB, k0 + kB);
                LDM_X4(bh[p][0], bh[p][1], bh[p][2], bh[p][3], sb + SM_BH + off);
                LDM_X4(bl[p][0], bl[p][1], bl[p][2], bl[p][3], sb + SM_BL + off);
            }
            #pragma unroll
            for (int mi = 0; mi < 2; mi++)
                #pragma unroll
                for (int nj = 0; nj < 4; nj++) {
                    int p = nj >> 1, s = (nj & 1) * 2;
                    MMA16816(acc[mi][nj], ah[mi][0], ah[mi][1], ah[mi][2], ah[mi][3], bh[p][s], bh[p][s + 1]);
                    MMA16816(acc[mi][nj], al_[mi][0], al_[mi][1], al_[mi][2], al_[mi][3], bh[p][s], bh[p][s + 1]);
                    MMA16816(acc[mi][nj], ah[mi][0], ah[mi][1], ah[mi][2], ah[mi][3], bl[p][s], bl[p][s + 1]);
                }
        }
    }

    int qr = lane >> 2, qc = (lane & 3) * 2;
    #pragma unroll
    for (int mi = 0; mi < 2; mi++) {
        int rin0 = mBase + mi * 16 + qr;
        #pragma unroll
        for (int nj = 0; nj < 4; nj++) {
            int c = n0 + nBase + nj * 8 + qc;
            if (m0 + rin0 < M)
                *(__half2*)(C + (size_t)(m0 + rin0) * HF + c) = __floats2half2_rn(acc[mi][nj][0], acc[mi][nj][1]);
            if (m0 + rin0 + 8 < M)
                *(__half2*)(C + (size_t)(m0 + rin0 + 8) * HF + c) = __floats2half2_rn(acc[mi][nj][2], acc[mi][nj][3]);
        }
    }

    // fused attention logits
    {
        int head = n0 >> 7;
        int base = n0 & 127;
        const float* alp = al + head * 128 + base;
        const float* arp = ar + head * 128 + base;
        float elv[4] = {0.f, 0.f, 0.f, 0.f};
        float erv[4] = {0.f, 0.f, 0.f, 0.f};
        #pragma unroll
        for (int mi = 0; mi < 2; mi++)
            #pragma unroll
            for (int nj = 0; nj < 4; nj++) {
                int cc = nBase + nj * 8 + qc;
                float w0 = alp[cc], w1 = alp[cc + 1];
                float u0 = arp[cc], u1 = arp[cc + 1];
                elv[mi * 2 + 0] += acc[mi][nj][0] * w0 + acc[mi][nj][1] * w1;
                elv[mi * 2 + 1] += acc[mi][nj][2] * w0 + acc[mi][nj][3] * w1;
                erv[mi * 2 + 0] += acc[mi][nj][0] * u0 + acc[mi][nj][1] * u1;
                erv[mi * 2 + 1] += acc[mi][nj][2] * u0 + acc[mi][nj][3] * u1;
            }
        #pragma unroll
        for (int t = 0; t < 4; t++) {
            elv[t] += __shfl_xor_sync(0xFFFFFFFFu, elv[t], 1);
            elv[t] += __shfl_xor_sync(0xFFFFFFFFu, elv[t], 2);
            erv[t] += __shfl_xor_sync(0xFFFFFFFFu, erv[t], 1);
            erv[t] += __shfl_xor_sync(0xFFFFFFFFu, erv[t], 2);
        }
        if ((lane & 3) == 0) {
            #pragma unroll
            for (int t = 0; t < 4; t++) {
                int r = m0 + mBase + (t >> 1) * 16 + qr + (t & 1) * 8;
                if (r < M) {
                    atomicAdd(&elOut[r * HEADS + head], elv[t]);
                    atomicAdd(&erOut[r * HEADS + head], erv[t]);
                }
            }
        }
    }
}

// ================= fused MLP (4 layers) + classifier head =================
#define MM_AH 0
#define MM_AL 16384
#define MM_WH 32768
#define MM_WL 65536
#define MM_TOTAL 98304

__global__ void __launch_bounds__(256, 2) k_mlp(
    const char* __restrict__ Ah, const char* __restrict__ Al,
    const float* __restrict__ b1, const float* __restrict__ b2,
    const float* __restrict__ b3, const float* __restrict__ b4,
    const float* __restrict__ w5, const float* __restrict__ bb5,
    float* __restrict__ out, int M)
{
    extern __shared__ char smem[];
    const uint32_t sb = smem_u32(smem);
    int tid = threadIdx.x;
    int m0 = blockIdx.x * 64;
    int blk128 = blockIdx.x >> 1, half = blockIdx.x & 1;

    {
        const char* sAh = Ah + (size_t)blk128 * 32768 + half * 16384;
        const char* sAl = Al + (size_t)blk128 * 32768 + half * 16384;
        const char* sWh = g_wh + (size_t)12 * 16384;
        const char* sWl = g_wl + (size_t)12 * 16384;
        #pragma unroll
        for (int i = 0; i < 4; i++) {
            int o = (tid + i * 256) * 16;
            CPA(sb + MM_AH + o, sAh + o);
            CPA(sb + MM_AL + o, sAl + o);
        }
        #pragma unroll
        for (int i = 0; i < 8; i++) {
            int o = (tid + i * 256) * 16;
            CPA(sb + MM_WH + o, sWh + o);
            CPA(sb + MM_WL + o, sWl + o);
        }
        CPA_COMMIT();
        asm volatile("cp.async.wait_group 0;" ::: "memory");
    }
    __syncthreads();

    int wid = tid >> 5, lane = tid & 31;
    int wr = wid >> 2, wc = wid & 3;
    int mBase = wr * 32, nBase = wc * 32;
    int tsel = nBase >> 6, nloc = nBase & 63;

    int rA = (lane & 7) + ((lane >> 3) & 1) * 8;
    int kA = (lane >> 4) * 8;
    int nB = ((lane >> 4) & 1) * 8 + (lane & 7);
    int kB = ((lane >> 3) & 1) * 8;
    int qr = lane >> 2, qc = (lane & 3) * 2;

    #pragma unroll 1
    for (int l = 0; l < 4; l++) {
        const float* bias = (l == 0) ? b1 : (l == 1) ? b2 : (l == 2) ? b3 : b4;

        float acc[2][4][4];
        #pragma unroll
        for (int i = 0; i < 2; i++)
            #pragma unroll
            for (int j = 0; j < 4; j++)
                #pragma unroll
                for (int t = 0; t < 4; t++) acc[i][j][t] = 0.f;

        #pragma unroll
        for (int kk = 0; kk < 8; kk++) {
            int k0 = kk * 16;
            uint32_t ah[2][4], al_[2][4], bh[2][4], bl[2][4];
            #pragma unroll
            for (int mi = 0; mi < 2; mi++) {
                uint32_t off = swz(mBase + mi * 16 + rA, k0 + kA);
                LDM_X4(ah[mi][0], ah[mi][1], ah[mi][2], ah[mi][3], sb + MM_AH + off);
                LDM_X4(al_[mi][0], al_[mi][1], al_[mi][2], al_[mi][3], sb + MM_AL + off);
            }
            #pragma unroll
            for (int p = 0; p < 2; p++) {
                uint32_t off = tsel * 16384 + swz(nloc + p * 16 + nB, k0 + kB);
                LDM_X4(bh[p][0], bh[p][1], bh[p][2], bh[p][3], sb + MM_WH + off);
                LDM_X4(bl[p][0], bl[p][1], bl[p][2], bl[p][3], sb + MM_WL + off);
            }
            #pragma unroll
            for (int mi = 0; mi < 2; mi++)
                #pragma unroll
                for (int nj = 0; nj < 4; nj++) {
                    int p = nj >> 1, s = (nj & 1) * 2;
                    MMA16816(acc[mi][nj], ah[mi][0], ah[mi][1], ah[mi][2], ah[mi][3], bh[p][s], bh[p][s + 1]);
                    MMA16816(acc[mi][nj], al_[mi][0], al_[mi][1], al_[mi][2], al_[mi][3], bh[p][s], bh[p][s + 1]);
                    MMA16816(acc[mi][nj], ah[mi][0], ah[mi][1], ah[mi][2], ah[mi][3], bl[p][s], bl[p][s + 1]);
                }
        }

        #pragma unroll
        for (int mi = 0; mi < 2; mi++)
            #pragma unroll
            for (int nj = 0; nj < 4; nj++) {
                int c = nBase + nj * 8 + qc;
                float bc0 = bias[c], bc1 = bias[c + 1];
                float v;
                v = acc[mi][nj][0] + bc0; acc[mi][nj][0] = v > 0.f ? v : 0.01f * v;
                v = acc[mi][nj][1] + bc1; acc[mi][nj][1] = v > 0.f ? v : 0.01f * v;
                v = acc[mi][nj][2] + bc0; acc[mi][nj][2] = v > 0.f ? v : 0.01f * v;
                v = acc[mi][nj][3] + bc1; acc[mi][nj][3] = v > 0.f ? v : 0.01f * v;
            }

        __syncthreads();

        if (l < 3) {
            #pragma unroll
            for (int mi = 0; mi < 2; mi++)
                #pragma unroll
                for (int nj = 0; nj < 4; nj++) {
                    int c = nBase + nj * 8 + qc;
                    int r0 = mBase + mi * 16 + qr;
                    __nv_bfloat16 h0, l0, h1, l1;
                    split_bf(acc[mi][nj][0], h0, l0); split_bf(acc[mi][nj][1], h1, l1);
                    uint32_t o = swz(r0, c);
                    *(__nv_bfloat162*)(smem + MM_AH + o) = __nv_bfloat162(h0, h1);
                    *(__nv_bfloat162*)(smem + MM_AL + o) = __nv_bfloat162(l0, l1);
                    split_bf(acc[mi][nj][2], h0, l0); split_bf(acc[mi][nj][3], h1, l1);
                    o = swz(r0 + 8, c);
                    *(__nv_bfloat162*)(smem + MM_AH + o) = __nv_bfloat162(h0, h1);
                    *(__nv_bfloat162*)(smem + MM_AL + o) = __nv_bfloat162(l0, l1);
                }
            const char* sWh = g_wh + (size_t)(14 + 2 * l) * 16384;
            const char* sWl = g_wl + (size_t)(14 + 2 * l) * 16384;
            #pragma unroll
            for (int i = 0; i < 8; i++) {
                int o = (tid + i * 256) * 16;
                CPA(sb + MM_WH + o, sWh + o);
                CPA(sb + MM_WL + o, sWl + o);
            }
            CPA_COMMIT();
            asm volatile("cp.async.wait_group 0;" ::: "memory");
            __syncthreads();
        } else {
            float* X = (float*)(smem + MM_WH);
            #pragma unroll
            for (int mi = 0; mi < 2; mi++)
                #pragma unroll
                for (int nj = 0; nj < 4; nj++) {
                    int c = nBase + nj * 8 + qc;
                    int r0 = mBase + mi * 16 + qr;
                    *(float2*)(X + r0 * 128 + c)       = make_float2(acc[mi][nj][0], acc[mi][nj][1]);
                    *(float2*)(X + (r0 + 8) * 128 + c) = make_float2(acc[mi][nj][2], acc[mi][nj][3]);
                }
            __syncthreads();
            for (int r = wid; r < 64; r += 8) {
                int row = m0 + r;
                float4 xv = ((const float4*)(X + r * 128))[lane];
                float s[NCLS];
                #pragma unroll
                for (int c = 0; c < NCLS; c++) {
                    s[c] = xv.x * w5[(lane * 4 + 0) * NCLS + c]
                         + xv.y * w5[(lane * 4 + 1) * NCLS + c]
                         + xv.z * w5[(lane * 4 + 2) * NCLS + c]
                         + xv.w * w5[(lane * 4 + 3) * NCLS + c];
                }
                #pragma unroll
                for (int o = 16; o; o >>= 1)
                    #pragma unroll
                    for (int c = 0; c < NCLS; c++)
                        s[c] += __shfl_xor_sync(0xFFFFFFFFu, s[c], o);
                if (lane < NCLS && row < M)
                    out[(size_t)row * NCLS + lane] = s[lane] + bb5[lane];
            }
        }
    }
}

// ---------------- fused per-dst softmax + aggregation (unroll-4, fp16 h) ----------------
__global__ void __launch_bounds__(256) k_gather(
    const float* __restrict__ elR, const float* __restrict__ erR,
    float* __restrict__ elZ, float* __restrict__ erZ,
    const float* __restrict__ bias,
    char* __restrict__ oBh, char* __restrict__ oBl)
{
    int gw = (blockIdx.x * blockDim.x + threadIdx.x) >> 5;
    int lane = threadIdx.x & 31;
    if (gw >= N_NODES) return;
    int beg = g_rowptr[gw], end = g_rowptr[gw + 1];

    if (elZ) {
        if (lane < HEADS)          elZ[gw * HEADS + lane] = 0.f;
        else if (lane < 2 * HEADS) erZ[gw * HEADS + lane - HEADS] = 0.f;
    }

    float er0 = erR[gw * HEADS + 0];
    float er1 = erR[gw * HEADS + 1];
    float er2 = erR[gw * HEADS + 2];

    float4 a0 = make_float4(0.f, 0.f, 0.f, 0.f), a1 = a0, a2 = a0;
    float d0 = 0.f, d1 = 0.f, d2 = 0.f;

    int i = beg;
    // unrolled-by-4 main loop: batch all loads to raise MLP
    for (; i + 4 <= end; i += 4) {
        int ss[4];
        #pragma unroll
        for (int u = 0; u < 4; u++) ss[u] = g_csrc[i + u];

        // batched h-row loads (12 independent 8B loads in flight)
        uint2 hb[4][3];
        #pragma unroll
        for (int u = 0; u < 4; u++) {
            const uint2* hp = (const uint2*)(g_h + (size_t)ss[u] * HF);
            hb[u][0] = hp[lane];
            hb[u][1] = hp[32 + lane];
            hb[u][2] = hp[64 + lane];
        }
        // batched logit loads + exp
        float p[4][3];
        #pragma unroll
        for (int u = 0; u < 4; u++) {
            float e0 = elR[ss[u] * HEADS + 0] + er0;
            float e1 = elR[ss[u] * HEADS + 1] + er1;
            float e2 = elR[ss[u] * HEADS + 2] + er2;
            p[u][0] = __expf(lrelu2(e0));
            p[u][1] = __expf(lrelu2(e1));
            p[u][2] = __expf(lrelu2(e2));
        }
        #pragma unroll
        for (int u = 0; u < 4; u++) {
            float p0 = p[u][0], p1 = p[u][1], p2 = p[u][2];
            d0 += p0; d1 += p1; d2 += p2;
            float2 f;
            f = __half22float2(*(__half2*)&hb[u][0].x); a0.x += p0 * f.x; a0.y += p0 * f.y;
            f = __half22float2(*(__half2*)&hb[u][0].y); a0.z += p0 * f.x; a0.w += p0 * f.y;
            f = __half22float2(*(__half2*)&hb[u][1].x); a1.x += p1 * f.x; a1.y += p1 * f.y;
            f = __half22float2(*(__half2*)&hb[u][1].y); a1.z += p1 * f.x; a1.w += p1 * f.y;
            f = __half22float2(*(__half2*)&hb[u][2].x); a2.x += p2 * f.x; a2.y += p2 * f.y;
            f = __half22float2(*(__half2*)&hb[u][2].y); a2.z += p2 * f.x; a2.w += p2 * f.y;
        }
    }
    // tail
    for (; i < end; i++) {
        int s = g_csrc[i];
        float e0 = elR[s * HEADS + 0] + er0;
        float e1 = elR[s * HEADS + 1] + er1;
        float e2 = elR[s * HEADS + 2] + er2;
        float p0 = __expf(lrelu2(e0)), p1 = __expf(lrelu2(e1)), p2 = __expf(lrelu2(e2));
        d0 += p0; d1 += p1; d2 += p2;
        const uint2* hp = (const uint2*)(g_h + (size_t)s * HF);
        uint2 u0 = hp[lane], u1 = hp[32 + lane], u2 = hp[64 + lane];
        float2 f;
        f = __half22float2(*(__half2*)&u0.x); a0.x += p0 * f.x; a0.y += p0 * f.y;
        f = __half22float2(*(__half2*)&u0.y); a0.z += p0 * f.x; a0.w += p0 * f.y;
        f = __half22float2(*(__half2*)&u1.x); a1.x += p1 * f.x; a1.y += p1 * f.y;
        f = __half22float2(*(__half2*)&u1.y); a1.z += p1 * f.x; a1.w += p1 * f.y;
        f = __half22float2(*(__half2*)&u2.x); a2.x += p2 * f.x; a2.y += p2 * f.y;
        f = __half22float2(*(__half2*)&u2.y); a2.z += p2 * f.x; a2.w += p2 * f.y;
    }

    float i0 = 1.f / (d0 + 1e-9f);
    float i1 = 1.f / (d1 + 1e-9f);
    float i2 = 1.f / (d2 + 1e-9f);

    float4 b0 = *(const float4*)(bias + 0 * HID + lane * 4);
    float4 b1 = *(const float4*)(bias + 1 * HID + lane * 4);
    float4 b2 = *(const float4*)(bias + 2 * HID + lane * 4);

    float4 o;
    float v;
    v = a0.x * i0 + b0.x; v = v > 0.f ? v : 0.01f * v; o.x  = v;
    v = a1.x * i1 + b1.x; v = v > 0.f ? v : 0.01f * v; o.x += v;
    v = a2.x * i2 + b2.x; v = v > 0.f ? v : 0.01f * v; o.x += v;
    v = a0.y * i0 + b0.y; v = v > 0.f ? v : 0.01f * v; o.y  = v;
    v = a1.y * i1 + b1.y; v = v > 0.f ? v : 0.01f * v; o.y += v;
    v = a2.y * i2 + b2.y; v = v > 0.f ? v : 0.01f * v; o.y += v;
    v = a0.z * i0 + b0.z; v = v > 0.f ? v : 0.01f * v; o.z  = v;
    v = a1.z * i1 + b1.z; v = v > 0.f ? v : 0.01f * v; o.z += v;
    v = a2.z * i2 + b2.z; v = v > 0.f ? v : 0.01f * v; o.z += v;
    v = a0.w * i0 + b0.w; v = v > 0.f ? v : 0.01f * v; o.w  = v;
    v = a1.w * i1 + b1.w; v = v > 0.f ? v : 0.01f * v; o.w += v;
    v = a2.w * i2 + b2.w; v = v > 0.f ? v : 0.01f * v; o.w += v;
    const float third = 1.f / 3.f;
    o.x *= third; o.y *= third; o.z *= third; o.w *= third;

    int blk = gw >> 7, rin = gw & 127, k = lane * 4;
    char* oh = oBh + (size_t)blk * 32768;
    char* ol = oBl + (size_t)blk * 32768;
    __nv_bfloat16 hx, hy, hz, hw, lx, ly, lz, lw;
    split_bf(o.x, hx, lx); split_bf(o.y, hy, ly);
    split_bf(o.z, hz, lz); split_bf(o.w, hw, lw);
    uint32_t s0 = swz(rin, k), s1 = swz(rin, k + 2);
    *(__nv_bfloat162*)(oh + s0) = __nv_bfloat162(hx, hy);
    *(__nv_bfloat162*)(oh + s1) = __nv_bfloat162(hz, hw);
    *(__nv_bfloat162*)(ol + s0) = __nv_bfloat162(lx, ly);
    *(__nv_bfloat162*)(ol + s1) = __nv_bfloat162(lz, lw);
}

// ---------------- host ----------------
extern "C" void kernel_launch(void* const* d_in, const int* in_sizes, int n_in,
                              void* d_out, int out_size)
{
    const float* in_feat = (const float*)d_in[0];
    const int*   src     = (const int*)  d_in[1];
    const int*   dst     = (const int*)  d_in[2];
    const float* W1  = (const float*)d_in[3];
    const float* al1 = (const float*)d_in[4];
    const float* ar1 = (const float*)d_in[5];
    const float* b1  = (const float*)d_in[6];
    const float* W2  = (const float*)d_in[7];
    const float* al2 = (const float*)d_in[8];
    const float* ar2 = (const float*)d_in[9];
    const float* b2  = (const float*)d_in[10];
    const float* lw1 = (const float*)d_in[11];
    const float* lb1 = (const float*)d_in[12];
    const float* lw2 = (const float*)d_in[13];
    const float* lb2 = (const float*)d_in[14];
    const float* lw3 = (const float*)d_in[15];
    const float* lb3 = (const float*)d_in[16];
    const float* lw4 = (const float*)d_in[17];
    const float* lb4 = (const float*)d_in[18];
    const float* lw5 = (const float*)d_in[19];
    const float* lb5 = (const float*)d_in[20];

    __half *p_h;
    float *p_el, *p_er;
    char *pAh, *pAl, *pBh, *pBl;
    cudaGetSymbolAddress((void**)&p_h,  g_h);
    cudaGetSymbolAddress((void**)&p_el, g_el);
    cudaGetSymbolAddress((void**)&p_er, g_er);
    cudaGetSymbolAddress((void**)&pAh, g_fAh);
    cudaGetSymbolAddress((void**)&pAl, g_fAl);
    cudaGetSymbolAddress((void**)&pBh, g_fBh);
    cudaGetSymbolAddress((void**)&pBl, g_fBl);
    float* el0 = p_el;                   float* er0 = p_er;
    float* el1 = p_el + N_NODES * HEADS; float* er1 = p_er + N_NODES * HEADS;

    cudaFuncSetAttribute((const void*)gemm_proj, cudaFuncAttributeMaxDynamicSharedMemorySize, SM_TOTAL);
    cudaFuncSetAttribute((const void*)k_mlp,     cudaFuncAttributeMaxDynamicSharedMemorySize, MM_TOTAL);

    k_conv_w<<<dim3(6, 6), 256>>>(W1, W2, lw1, lw2, lw3, lw4);
    k_conv_a<<<MTILES + CNT_BLKS, 256>>>(in_feat, dst, N_NODES);
    k_scan<<<1, 1024>>>();
    gemm_proj<<<dim3(MTILES + SCT_X, 6), 256, SM_TOTAL>>>(pAh, pAl, 0, al1, ar1,
                                                          el0, er0, src, dst, p_h, N_NODES);
    k_gather<<<(N_NODES * 32 + 255) / 256, 256>>>(el0, er0, el1, er1, b1, pBh, pBl);
    gemm_proj<<<dim3(MTILES, 6), 256, SM_TOTAL>>>(pBh, pBl, 6, al2, ar2,
                                                  el1, er1, nullptr, nullptr, p_h, N_NODES);
    k_gather<<<(N_NODES * 32 + 255) / 256, 256>>>(el1, er1, nullptr, nullptr, b2, pAh, pAl);
    k_mlp<<<(N_NODES + 63) / 64, 256, MM_TOTAL>>>(pAh, pAl, lb1, lb2, lb3, lb4, lw5, lb5,
                                                  (float*)d_out, N_NODES);
}

// round 17
// speedup vs baseline: 1.5134x; 1.5134x over previous
#include <cuda_runtime.h>
#include <cuda_bf16.h>
#include <cuda_fp16.h>
#include <math.h>
#include <cstdint>

#define N_NODES 50000
#define N_EDGES 800000
#define HEADS   3
#define HID     128
#define HF      (HEADS*HID)   // 384
#define NCLS    6
#define MTILES  ((N_NODES + 127) / 128)   // 391
#define CNT_BLKS 784      // count blocks in conv_a (784*1024 >= E)
#define SCT_X    131      // scatter grid columns in proj1 (131*6*1024 >= E)

// ---------------- scratch ----------------
__device__ __half g_h [(size_t)N_NODES*HF];   // projected features fp16
__device__ float g_el [2][N_NODES*HEADS];     // attention logit sets (layer1 / layer2)
__device__ float g_er [2][N_NODES*HEADS];
__device__ int   g_deg   [N_NODES];
__device__ int   g_rowptr[N_NODES + 1];
__device__ int   g_cursor[N_NODES];
__device__ int   g_csrc  [N_EDGES];

__device__ __align__(16) char g_fAh[(size_t)MTILES*32768];
__device__ __align__(16) char g_fAl[(size_t)MTILES*32768];
__device__ __align__(16) char g_fBh[(size_t)MTILES*32768];
__device__ __align__(16) char g_fBl[(size_t)MTILES*32768];
__device__ __align__(16) char g_wh [20*16384];
__device__ __align__(16) char g_wl [20*16384];

__device__ __forceinline__ uint32_t smem_u32(const void* p) {
    uint32_t a;
    asm("{ .reg .u64 t; cvta.to.shared.u64 t, %1; cvt.u32.u64 %0, t; }" : "=r"(a) : "l"(p));
    return a;
}
__device__ __forceinline__ uint32_t swz(int r, int k) {
    return (uint32_t)((r << 8) + (((((unsigned)k >> 3) & 15) ^ (r & 7)) << 4) + ((k & 7) << 1));
}
__device__ __forceinline__ void split_bf(float v, __nv_bfloat16& h, __nv_bfloat16& l) {
    h = __float2bfloat16_rn(v);
    l = __float2bfloat16_rn(v - __bfloat162float(h));
}
__device__ __forceinline__ float lrelu2(float v) { return v > 0.f ? v : 0.2f * v; }

#define CPA(dst, src) asm volatile("cp.async.cg.shared.global [%0], [%1], 16;" :: "r"(dst), "l"(src))
#define CPA_COMMIT()  asm volatile("cp.async.commit_group;")
#define LDM_X4(r0, r1, r2, r3, a) \
    asm volatile("ldmatrix.sync.aligned.m8n8.x4.shared.b16 {%0,%1,%2,%3}, [%4];" \
                 : "=r"(r0), "=r"(r1), "=r"(r2), "=r"(r3) : "r"(a))
#define MMA16816(d, a0, a1, a2, a3, b0, b1) \
    asm volatile("mma.sync.aligned.m16n8k16.row.col.f32.bf16.bf16.f32 " \
                 "{%0,%1,%2,%3}, {%4,%5,%6,%7}, {%8,%9}, {%0,%1,%2,%3};" \
                 : "+f"((d)[0]), "+f"((d)[1]), "+f"((d)[2]), "+f"((d)[3]) \
                 : "r"(a0), "r"(a1), "r"(a2), "r"(a3), "r"(b0), "r"(b1))

// ---------------- weights conversion + init zeroing ----------------
__global__ void k_conv_w(const float* W1, const float* W2, const float* l1,
                         const float* l2, const float* l3, const float* l4)
{
    int m = blockIdx.y, t = blockIdx.x;
    int flat = (blockIdx.y * gridDim.x + blockIdx.x) * 256 + threadIdx.x; // 9216 threads
    for (int i = flat; i < N_NODES; i += 9216) g_deg[i] = 0;
    for (int i = flat; i < N_NODES * HEADS; i += 9216) { g_el[0][i] = 0.f; g_er[0][i] = 0.f; }

    const float* W; int Nc, base;
    if (m == 0)      { W = W1; Nc = HF;  base = 0; }
    else if (m == 1) { W = W2; Nc = HF;  base = 6; }
    else { W = (m == 2) ? l1 : (m == 3) ? l2 : (m == 4) ? l3 : l4; Nc = HID; base = 12 + (m - 2) * 2; }
    if (t * 64 >= Nc) return;
    char* oh = g_wh + (size_t)(base + t) * 16384;
    char* ol = g_wl + (size_t)(base + t) * 16384;
    #pragma unroll
    for (int e = 0; e < 32; e++) {
        int idx = threadIdx.x + e * 256;
        int n = idx >> 7, k = idx & 127;
        float v = W[(size_t)k * Nc + t * 64 + n];
        __nv_bfloat16 h, l;
        split_bf(v, h, l);
        uint32_t o = swz(n, k);
        *(__nv_bfloat16*)(oh + o) = h;
        *(__nv_bfloat16*)(ol + o) = l;
    }
}

// ---------------- input conversion + fused degree count ----------------
__global__ void k_conv_a(const float* __restrict__ A, const int* __restrict__ dst, int M)
{
    int blk = blockIdx.x;
    if (blk >= MTILES) {
        int base = (blk - MTILES) * 1024;
        #pragma unroll
        for (int j = 0; j < 4; j++) {
            int e = base + j * 256 + threadIdx.x;
            if (e < N_EDGES) atomicAdd(&g_deg[dst[e]], 1);
        }
        return;
    }
    char* oh = g_fAh + (size_t)blk * 32768;
    char* ol = g_fAl + (size_t)blk * 32768;
    int m0 = blk * 128;
    #pragma unroll
    for (int it = 0; it < 16; it++) {
        int f = threadIdx.x + it * 256;
        int row = f >> 5, kq = (f & 31) << 2;
        float4 v = make_float4(0.f, 0.f, 0.f, 0.f);
        if (m0 + row < M) v = *(const float4*)(A + (size_t)(m0 + row) * 128 + kq);
        __nv_bfloat16 hx, hy, hz, hw, lx, ly, lz, lw;
        split_bf(v.x, hx, lx); split_bf(v.y, hy, ly);
        split_bf(v.z, hz, lz); split_bf(v.w, hw, lw);
        uint32_t o0 = swz(row, kq), o1 = swz(row, kq + 2);
        *(__nv_bfloat162*)(oh + o0) = __nv_bfloat162(hx, hy);
        *(__nv_bfloat162*)(oh + o1) = __nv_bfloat162(hz, hw);
        *(__nv_bfloat162*)(ol + o0) = __nv_bfloat162(lx, ly);
        *(__nv_bfloat162*)(ol + o1) = __nv_bfloat162(lz, lw);
    }
}

__global__ void k_scan() {
    const int T = 1024;
    const int C = (N_NODES + T - 1) / T;
    __shared__ int s[T];
    int t = threadIdx.x;
    int beg = t * C, end = min(beg + C, N_NODES);
    int sum = 0;
    for (int i = beg; i < end; i++) sum += g_deg[i];
    s[t] = sum;
    __syncthreads();
    for (int off = 1; off < T; off <<= 1) {
        int v = (t >= off) ? s[t - off] : 0;
        __syncthreads();
        s[t] += v;
        __syncthreads();
    }
    int run = (t > 0) ? s[t - 1] : 0;
    for (int i = beg; i < end; i++) {
        g_rowptr[i] = run;
        g_cursor[i] = run;
        run += g_deg[i];
    }
    if (t == T - 1) g_rowptr[N_NODES] = run;
}

// ================= projection GEMM (bf16x3, pipelined) + optional fused edge scatter =================
#define SM_AH 0
#define SM_AL 32768
#define SM_BH 65536
#define SM_BL 81920
#define SM_TOTAL 98304

__global__ void __launch_bounds__(256, 2) gemm_proj(
    const char* __restrict__ Ah, const char* __restrict__ Al, int wbase,
    const float* __restrict__ al, const float* __restrict__ ar,
    float* __restrict__ elOut, float* __restrict__ erOut,
    const int* __restrict__ src, const int* __restrict__ dst,
    __half* __restrict__ C, int M)
{
    extern __shared__ char smem[];
    const uint32_t sb = smem_u32(smem);
    int tid = threadIdx.x;

    if (blockIdx.x >= MTILES) {
        int slice = (blockIdx.x - MTILES) * 6 + blockIdx.y;
        int base = slice * 1024;
        #pragma unroll
        for (int j = 0; j < 4; j++) {
            int e = base + j * 256 + tid;
            if (e < N_EDGES) {
                int pos = atomicAdd(&g_cursor[dst[e]], 1);
                g_csrc[pos] = src[e];
            }
        }
        return;
    }

    int m0 = blockIdx.x * 128, n0 = blockIdx.y * 64;

    {
        const char* sAh = Ah + (size_t)blockIdx.x * 32768;
        const char* sAl = Al + (size_t)blockIdx.x * 32768;
        const char* sBh = g_wh + (size_t)(wbase + blockIdx.y) * 16384;
        const char* sBl = g_wl + (size_t)(wbase + blockIdx.y) * 16384;
        #pragma unroll
        for (int half = 0; half < 2; half++) {
            #pragma unroll
            for (int i = 0; i < 4; i++) {
                int idx = tid + i * 256;
                int o = (idx >> 3) * 256 + half * 128 + (idx & 7) * 16;
                CPA(sb + SM_AH + o, sAh + o);
                CPA(sb + SM_AL + o, sAl + o);
            }
            #pragma unroll
            for (int i = 0; i < 2; i++) {
                int idx = tid + i * 256;
                int o = (idx >> 3) * 256 + half * 128 + (idx & 7) * 16;
                CPA(sb + SM_BH + o, sBh + o);
                CPA(sb + SM_BL + o, sBl + o);
            }
            CPA_COMMIT();
        }
    }

    int wid = tid >> 5, lane = tid & 31;
    int wr = wid >> 1, wc = wid & 1;
    int mBase = wr * 32, nBase = wc * 32;

    float acc[2][4][4];
    #pragma unroll
    for (int i = 0; i < 2; i++)
        #pragma unroll
        for (int j = 0; j < 4; j++)
            #pragma unroll
            for (int t = 0; t < 4; t++) acc[i][j][t] = 0.f;

    int rA = (lane & 7) + ((lane >> 3) & 1) * 8;
    int kA = (lane >> 4) * 8;
    int nB = ((lane >> 4) & 1) * 8 + (lane & 7);
    int kB = ((lane >> 3) & 1) * 8;

    #pragma unroll
    for (int ph = 0; ph < 2; ph++) {
        if (ph == 0) { asm volatile("cp.async.wait_group 1;" ::: "memory"); }
        else         { asm volatile("cp.async.wait_group 0;" ::: "memory"); }
        __syncthreads();
        #pragma unroll
        for (int kk = ph * 4; kk < ph * 4 + 4; kk++) {
            int k0 = kk * 16;
            uint32_t ah[2][4], al_[2][4], bh[2][4], bl[2][4];
            #pragma unroll
            for (int mi = 0; mi < 2; mi++) {
                uint32_t off = swz(mBase + mi * 16 + rA, k0 + kA);
                LDM_X4(ah[mi][0], ah[mi][1], ah[mi][2], ah[mi][3], sb + SM_AH + off);
                LDM_X4(al_[mi][0], al_[mi][1], al_[mi][2], al_[mi][3], sb + SM_AL + off);
            }
            #pragma unroll
            for (int p = 0; p < 2; p++) {
                uint32_t off = swz(nBase + p * 16 + nB, k0 + kB);
                LDM_X4(bh[p][0], bh[p][1], bh[p][2], bh[p][3], sb + SM_BH + off);
                LDM_X4(bl[p][0], bl[p][1], bl[p][2], bl[p][3], sb + SM_BL + off);
            }
            #pragma unroll
            for (int mi = 0; mi < 2; mi++)
                #pragma unroll
                for (int nj = 0; nj < 4; nj++) {
                    int p = nj >> 1, s = (nj & 1) * 2;
                    MMA16816(acc[mi][nj], ah[mi][0], ah[mi][1], ah[mi][2], ah[mi][3], bh[p][s], bh[p][s + 1]);
                    MMA16816(acc[mi][nj], al_[mi][0], al_[mi][1], al_[mi][2], al_[mi][3], bh[p][s], bh[p][s + 1]);
                    MMA16816(acc[mi][nj], ah[mi][0], ah[mi][1], ah[mi][2], ah[mi][3], bl[p][s], bl[p][s + 1]);
                }
        }
    }

    int qr = lane >> 2, qc = (lane & 3) * 2;
    #pragma unroll
    for (int mi = 0; mi < 2; mi++) {
        int rin0 = mBase + mi * 16 + qr;
        #pragma unroll
        for (int nj = 0; nj < 4; nj++) {
            int c = n0 + nBase + nj * 8 + qc;
            if (m0 + rin0 < M)
                *(__half2*)(C + (size_t)(m0 + rin0) * HF + c) = __floats2half2_rn(acc[mi][nj][0], acc[mi][nj][1]);
            if (m0 + rin0 + 8 < M)
                *(__half2*)(C + (size_t)(m0 + rin0 + 8) * HF + c) = __floats2half2_rn(acc[mi][nj][2], acc[mi][nj][3]);
        }
    }

    // fused attention logits
    {
        int head = n0 >> 7;
        int base = n0 & 127;
        const float* alp = al + head * 128 + base;
        const float* arp = ar + head * 128 + base;
        float elv[4] = {0.f, 0.f, 0.f, 0.f};
        float erv[4] = {0.f, 0.f, 0.f, 0.f};
        #pragma unroll
        for (int mi = 0; mi < 2; mi++)
            #pragma unroll
            for (int nj = 0; nj < 4; nj++) {
                int cc = nBase + nj * 8 + qc;
                float w0 = alp[cc], w1 = alp[cc + 1];
                float u0 = arp[cc], u1 = arp[cc + 1];
                elv[mi * 2 + 0] += acc[mi][nj][0] * w0 + acc[mi][nj][1] * w1;
                elv[mi * 2 + 1] += acc[mi][nj][2] * w0 + acc[mi][nj][3] * w1;
                erv[mi * 2 + 0] += acc[mi][nj][0] * u0 + acc[mi][nj][1] * u1;
                erv[mi * 2 + 1] += acc[mi][nj][2] * u0 + acc[mi][nj][3] * u1;
            }
        #pragma unroll
        for (int t = 0; t < 4; t++) {
            elv[t] += __shfl_xor_sync(0xFFFFFFFFu, elv[t], 1);
            elv[t] += __shfl_xor_sync(0xFFFFFFFFu, elv[t], 2);
            erv[t] += __shfl_xor_sync(0xFFFFFFFFu, erv[t], 1);
            erv[t] += __shfl_xor_sync(0xFFFFFFFFu, erv[t], 2);
        }
        if ((lane & 3) == 0) {
            #pragma unroll
            for (int t = 0; t < 4; t++) {
                int r = m0 + mBase + (t >> 1) * 16 + qr + (t & 1) * 8;
                if (r < M) {
                    atomicAdd(&elOut[r * HEADS + head], elv[t]);
                    atomicAdd(&erOut[r * HEADS + head], erv[t]);
                }
            }
        }
    }
}

// ================= fused MLP (4 layers) + classifier head =================
#define MM_AH 0
#define MM_AL 16384
#define MM_WH 32768
#define MM_WL 65536
#define MM_TOTAL 98304

__global__ void __launch_bounds__(256, 2) k_mlp(
    const char* __restrict__ Ah, const char* __restrict__ Al,
    const float* __restrict__ b1, const float* __restrict__ b2,
    const float* __restrict__ b3, const float* __restrict__ b4,
    const float* __restrict__ w5, const float* __restrict__ bb5,
    float* __restrict__ out, int M)
{
    extern __shared__ char smem[];
    const uint32_t sb = smem_u32(smem);
    int tid = threadIdx.x;
    int m0 = blockIdx.x * 64;
    int blk128 = blockIdx.x >> 1, half = blockIdx.x & 1;

    {
        const char* sAh = Ah + (size_t)blk128 * 32768 + half * 16384;
        const char* sAl = Al + (size_t)blk128 * 32768 + half * 16384;
        const char* sWh = g_wh + (size_t)12 * 16384;
        const char* sWl = g_wl + (size_t)12 * 16384;
        #pragma unroll
        for (int i = 0; i < 4; i++) {
            int o = (tid + i * 256) * 16;
            CPA(sb + MM_AH + o, sAh + o);
            CPA(sb + MM_AL + o, sAl + o);
        }
        #pragma unroll
        for (int i = 0; i < 8; i++) {
            int o = (tid + i * 256) * 16;
            CPA(sb + MM_WH + o, sWh + o);
            CPA(sb + MM_WL + o, sWl + o);
        }
        CPA_COMMIT();
        asm volatile("cp.async.wait_group 0;" ::: "memory");
    }
    __syncthreads();

    int wid = tid >> 5, lane = tid & 31;
    int wr = wid >> 2, wc = wid & 3;
    int mBase = wr * 32, nBase = wc * 32;
    int tsel = nBase >> 6, nloc = nBase & 63;

    int rA = (lane & 7) + ((lane >> 3) & 1) * 8;
    int kA = (lane >> 4) * 8;
    int nB = ((lane >> 4) & 1) * 8 + (lane & 7);
    int kB = ((lane >> 3) & 1) * 8;
    int qr = lane >> 2, qc = (lane & 3) * 2;

    #pragma unroll 1
    for (int l = 0; l < 4; l++) {
        const float* bias = (l == 0) ? b1 : (l == 1) ? b2 : (l == 2) ? b3 : b4;

        float acc[2][4][4];
        #pragma unroll
        for (int i = 0; i < 2; i++)
            #pragma unroll
            for (int j = 0; j < 4; j++)
                #pragma unroll
                for (int t = 0; t < 4; t++) acc[i][j][t] = 0.f;

        #pragma unroll
        for (int kk = 0; kk < 8; kk++) {
            int k0 = kk * 16;
            uint32_t ah[2][4], al_[2][4], bh[2][4], bl[2][4];
            #pragma unroll
            for (int mi = 0; mi < 2; mi++) {
                uint32_t off = swz(mBase + mi * 16 + rA, k0 + kA);
                LDM_X4(ah[mi][0], ah[mi][1], ah[mi][2], ah[mi][3], sb + MM_AH + off);
                LDM_X4(al_[mi][0], al_[mi][1], al_[mi][2], al_[mi][3], sb + MM_AL + off);
            }
            #pragma unroll
            for (int p = 0; p < 2; p++) {
                uint32_t off = tsel * 16384 + swz(nloc + p * 16 + nB, k0 + kB);
                LDM_X4(bh[p][0], bh[p][1], bh[p][2], bh[p][3], sb + MM_WH + off);
                LDM_X4(bl[p][0], bl[p][1], bl[p][2], bl[p][3], sb + MM_WL + off);
            }
            #pragma unroll
            for (int mi = 0; mi < 2; mi++)
                #pragma unroll
                for (int nj = 0; nj < 4; nj++) {
                    int p = nj >> 1, s = (nj & 1) * 2;
                    MMA16816(acc[mi][nj], ah[mi][0], ah[mi][1], ah[mi][2], ah[mi][3], bh[p][s], bh[p][s + 1]);
                    MMA16816(acc[mi][nj], al_[mi][0], al_[mi][1], al_[mi][2], al_[mi][3], bh[p][s], bh[p][s + 1]);
                    MMA16816(acc[mi][nj], ah[mi][0], ah[mi][1], ah[mi][2], ah[mi][3], bl[p][s], bl[p][s + 1]);
                }
        }

        #pragma unroll
        for (int mi = 0; mi < 2; mi++)
            #pragma unroll
            for (int nj = 0; nj < 4; nj++) {
                int c = nBase + nj * 8 + qc;
                float bc0 = bias[c], bc1 = bias[c + 1];
                float v;
                v = acc[mi][nj][0] + bc0; acc[mi][nj][0] = v > 0.f ? v : 0.01f * v;
                v = acc[mi][nj][1] + bc1; acc[mi][nj][1] = v > 0.f ? v : 0.01f * v;
                v = acc[mi][nj][2] + bc0; acc[mi][nj][2] = v > 0.f ? v : 0.01f * v;
                v = acc[mi][nj][3] + bc1; acc[mi][nj][3] = v > 0.f ? v : 0.01f * v;
            }

        __syncthreads();

        if (l < 3) {
            #pragma unroll
            for (int mi = 0; mi < 2; mi++)
                #pragma unroll
                for (int nj = 0; nj < 4; nj++) {
                    int c = nBase + nj * 8 + qc;
                    int r0 = mBase + mi * 16 + qr;
                    __nv_bfloat16 h0, l0, h1, l1;
                    split_bf(acc[mi][nj][0], h0, l0); split_bf(acc[mi][nj][1], h1, l1);
                    uint32_t o = swz(r0, c);
                    *(__nv_bfloat162*)(smem + MM_AH + o) = __nv_bfloat162(h0, h1);
                    *(__nv_bfloat162*)(smem + MM_AL + o) = __nv_bfloat162(l0, l1);
                    split_bf(acc[mi][nj][2], h0, l0); split_bf(acc[mi][nj][3], h1, l1);
                    o = swz(r0 + 8, c);
                    *(__nv_bfloat162*)(smem + MM_AH + o) = __nv_bfloat162(h0, h1);
                    *(__nv_bfloat162*)(smem + MM_AL + o) = __nv_bfloat162(l0, l1);
                }
            const char* sWh = g_wh + (size_t)(14 + 2 * l) * 16384;
            const char* sWl = g_wl + (size_t)(14 + 2 * l) * 16384;
            #pragma unroll
            for (int i = 0; i < 8; i++) {
                int o = (tid + i * 256) * 16;
                CPA(sb + MM_WH + o, sWh + o);
                CPA(sb + MM_WL + o, sWl + o);
            }
            CPA_COMMIT();
            asm volatile("cp.async.wait_group 0;" ::: "memory");
            __syncthreads();
        } else {
            float* X = (float*)(smem + MM_WH);
            #pragma unroll
            for (int mi = 0; mi < 2; mi++)
                #pragma unroll
                for (int nj = 0; nj < 4; nj++) {
                    int c = nBase + nj * 8 + qc;
                    int r0 = mBase + mi * 16 + qr;
                    *(float2*)(X + r0 * 128 + c)       = make_float2(acc[mi][nj][0], acc[mi][nj][1]);
                    *(float2*)(X + (r0 + 8) * 128 + c) = make_float2(acc[mi][nj][2], acc[mi][nj][3]);
                }
            __syncthreads();
            for (int r = wid; r < 64; r += 8) {
                int row = m0 + r;
                float4 xv = ((const float4*)(X + r * 128))[lane];
                float s[NCLS];
                #pragma unroll
                for (int c = 0; c < NCLS; c++) {
                    s[c] = xv.x * w5[(lane * 4 + 0) * NCLS + c]
                         + xv.y * w5[(lane * 4 + 1) * NCLS + c]
                         + xv.z * w5[(lane * 4 + 2) * NCLS + c]
                         + xv.w * w5[(lane * 4 + 3) * NCLS + c];
                }
                #pragma unroll
                for (int o = 16; o; o >>= 1)
                    #pragma unroll
                    for (int c = 0; c < NCLS; c++)
                        s[c] += __shfl_xor_sync(0xFFFFFFFFu, s[c], o);
                if (lane < NCLS && row < M)
                    out[(size_t)row * NCLS + lane] = s[lane] + bb5[lane];
            }
        }
    }
}

// ---------------- fused per-dst softmax + aggregation (unroll-2, fp16 h) ----------------
__global__ void __launch_bounds__(256) k_gather(
    const float* __restrict__ elR, const float* __restrict__ erR,
    float* __restrict__ elZ, float* __restrict__ erZ,
    const float* __restrict__ bias,
    char* __restrict__ oBh, char* __restrict__ oBl)
{
    int gw = (blockIdx.x * blockDim.x + threadIdx.x) >> 5;
    int lane = threadIdx.x & 31;
    if (gw >= N_NODES) return;
    int beg = g_rowptr[gw], end = g_rowptr[gw + 1];

    if (elZ) {
        if (lane < HEADS)          elZ[gw * HEADS + lane] = 0.f;
        else if (lane < 2 * HEADS) erZ[gw * HEADS + lane - HEADS] = 0.f;
    }

    float er0 = erR[gw * HEADS + 0];
    float er1 = erR[gw * HEADS + 1];
    float er2 = erR[gw * HEADS + 2];

    float4 a0 = make_float4(0.f, 0.f, 0.f, 0.f), a1 = a0, a2 = a0;
    float d0 = 0.f, d1 = 0.f, d2 = 0.f;

    int i = beg;
    // unroll-2: batch loads of two edges to double memory-level parallelism
    for (; i + 2 <= end; i += 2) {
        int s0 = g_csrc[i], s1 = g_csrc[i + 1];
        const uint2* hpa = (const uint2*)(g_h + (size_t)s0 * HF);
        const uint2* hpb = (const uint2*)(g_h + (size_t)s1 * HF);
        uint2 ua0 = hpa[lane], ua1 = hpa[32 + lane], ua2 = hpa[64 + lane];
        uint2 ub0 = hpb[lane], ub1 = hpb[32 + lane], ub2 = hpb[64 + lane];
        float ea0 = elR[s0 * HEADS + 0] + er0;
        float ea1 = elR[s0 * HEADS + 1] + er1;
        float ea2 = elR[s0 * HEADS + 2] + er2;
        float eb0 = elR[s1 * HEADS + 0] + er0;
        float eb1 = elR[s1 * HEADS + 1] + er1;
        float eb2 = elR[s1 * HEADS + 2] + er2;
        float pa0 = __expf(lrelu2(ea0)), pa1 = __expf(lrelu2(ea1)), pa2 = __expf(lrelu2(ea2));
        float pb0 = __expf(lrelu2(eb0)), pb1 = __expf(lrelu2(eb1)), pb2 = __expf(lrelu2(eb2));
        d0 += pa0 + pb0; d1 += pa1 + pb1; d2 += pa2 + pb2;
        float2 f;
        f = __half22float2(*(__half2*)&ua0.x); a0.x += pa0 * f.x; a0.y += pa0 * f.y;
        f = __half22float2(*(__half2*)&ua0.y); a0.z += pa0 * f.x; a0.w += pa0 * f.y;
        f = __half22float2(*(__half2*)&ua1.x); a1.x += pa1 * f.x; a1.y += pa1 * f.y;
        f = __half22float2(*(__half2*)&ua1.y); a1.z += pa1 * f.x; a1.w += pa1 * f.y;
        f = __half22float2(*(__half2*)&ua2.x); a2.x += pa2 * f.x; a2.y += pa2 * f.y;
        f = __half22float2(*(__half2*)&ua2.y); a2.z += pa2 * f.x; a2.w += pa2 * f.y;
        f = __half22float2(*(__half2*)&ub0.x); a0.x += pb0 * f.x; a0.y += pb0 * f.y;
        f = __half22float2(*(__half2*)&ub0.y); a0.z += pb0 * f.x; a0.w += pb0 * f.y;
        f = __half22float2(*(__half2*)&ub1.x); a1.x += pb1 * f.x; a1.y += pb1 * f.y;
        f = __half22float2(*(__half2*)&ub1.y); a1.z += pb1 * f.x; a1.w += pb1 * f.y;
        f = __half22float2(*(__half2*)&ub2.x); a2.x += pb2 * f.x; a2.y += pb2 * f.y;
        f = __half22float2(*(__half2*)&ub2.y); a2.z += pb2 * f.x; a2.w += pb2 * f.y;
    }
    for (; i < end; i++) {
        int s = g_csrc[i];
        float e0 = elR[s * HEADS + 0] + er0;
        float e1 = elR[s * HEADS + 1] + er1;
        float e2 = elR[s * HEADS + 2] + er2;
        float p0 = __expf(lrelu2(e0)), p1 = __expf(lrelu2(e1)), p2 = __expf(lrelu2(e2));
        d0 += p0; d1 += p1; d2 += p2;
        const uint2* hp = (const uint2*)(g_h + (size_t)s * HF);
        uint2 u0 = hp[lane], u1 = hp[32 + lane], u2 = hp[64 + lane];
        float2 f;
        f = __half22float2(*(__half2*)&u0.x); a0.x += p0 * f.x; a0.y += p0 * f.y;
        f = __half22float2(*(__half2*)&u0.y); a0.z += p0 * f.x; a0.w += p0 * f.y;
        f = __half22float2(*(__half2*)&u1.x); a1.x += p1 * f.x; a1.y += p1 * f.y;
        f = __half22float2(*(__half2*)&u1.y); a1.z += p1 * f.x; a1.w += p1 * f.y;
        f = __half22float2(*(__half2*)&u2.x); a2.x += p2 * f.x; a2.y += p2 * f.y;
        f = __half22float2(*(__half2*)&u2.y); a2.z += p2 * f.x; a2.w += p2 * f.y;
    }

    float i0 = 1.f / (d0 + 1e-9f);
    float i1 = 1.f / (d1 + 1e-9f);
    float i2 = 1.f / (d2 + 1e-9f);

    float4 b0 = *(const float4*)(bias + 0 * HID + lane * 4);
    float4 b1 = *(const float4*)(bias + 1 * HID + lane * 4);
    float4 b2 = *(const float4*)(bias + 2 * HID + lane * 4);

    float4 o;
    float v;
    v = a0.x * i0 + b0.x; v = v > 0.f ? v : 0.01f * v; o.x  = v;
    v = a1.x * i1 + b1.x; v = v > 0.f ? v : 0.01f * v; o.x += v;
    v = a2.x * i2 + b2.x; v = v > 0.f ? v : 0.01f * v; o.x += v;
    v = a0.y * i0 + b0.y; v = v > 0.f ? v : 0.01f * v; o.y  = v;
    v = a1.y * i1 + b1.y; v = v > 0.f ? v : 0.01f * v; o.y += v;
    v = a2.y * i2 + b2.y; v = v > 0.f ? v : 0.01f * v; o.y += v;
    v = a0.z * i0 + b0.z; v = v > 0.f ? v : 0.01f * v; o.z  = v;
    v = a1.z * i1 + b1.z; v = v > 0.f ? v : 0.01f * v; o.z += v;
    v = a2.z * i2 + b2.z; v = v > 0.f ? v : 0.01f * v; o.z += v;
    v = a0.w * i0 + b0.w; v = v > 0.f ? v : 0.01f * v; o.w  = v;
    v = a1.w * i1 + b1.w; v = v > 0.f ? v : 0.01f * v; o.w += v;
    v = a2.w * i2 + b2.w; v = v > 0.f ? v : 0.01f * v; o.w += v;
    const float third = 1.f / 3.f;
    o.x *= third; o.y *= third; o.z *= third; o.w *= third;

    int blk = gw >> 7, rin = gw & 127, k = lane * 4;
    char* oh = oBh + (size_t)blk * 32768;
    char* ol = oBl + (size_t)blk * 32768;
    __nv_bfloat16 hx, hy, hz, hw, lx, ly, lz, lw;
    split_bf(o.x, hx, lx); split_bf(o.y, hy, ly);
    split_bf(o.z, hz, lz); split_bf(o.w, hw, lw);
    uint32_t s0 = swz(rin, k), s1 = swz(rin, k + 2);
    *(__nv_bfloat162*)(oh + s0) = __nv_bfloat162(hx, hy);
    *(__nv_bfloat162*)(oh + s1) = __nv_bfloat162(hz, hw);
    *(__nv_bfloat162*)(ol + s0) = __nv_bfloat162(lx, ly);
    *(__nv_bfloat162*)(ol + s1) = __nv_bfloat162(lz, lw);
}

// ---------------- host ----------------
extern "C" void kernel_launch(void* const* d_in, const int* in_sizes, int n_in,
                              void* d_out, int out_size)
{
    const float* in_feat = (const float*)d_in[0];
    const int*   src     = (const int*)  d_in[1];
    const int*   dst     = (const int*)  d_in[2];
    const float* W1  = (const float*)d_in[3];
    const float* al1 = (const float*)d_in[4];
    const float* ar1 = (const float*)d_in[5];
    const float* b1  = (const float*)d_in[6];
    const float* W2  = (const float*)d_in[7];
    const float* al2 = (const float*)d_in[8];
    const float* ar2 = (const float*)d_in[9];
    const float* b2  = (const float*)d_in[10];
    const float* lw1 = (const float*)d_in[11];
    const float* lb1 = (const float*)d_in[12];
    const float* lw2 = (const float*)d_in[13];
    const float* lb2 = (const float*)d_in[14];
    const float* lw3 = (const float*)d_in[15];
    const float* lb3 = (const float*)d_in[16];
    const float* lw4 = (const float*)d_in[17];
    const float* lb4 = (const float*)d_in[18];
    const float* lw5 = (const float*)d_in[19];
    const float* lb5 = (const float*)d_in[20];

    __half *p_h;
    float *p_el, *p_er;
    char *pAh, *pAl, *pBh, *pBl;
    cudaGetSymbolAddress((void**)&p_h,  g_h);
    cudaGetSymbolAddress((void**)&p_el, g_el);
    cudaGetSymbolAddress((void**)&p_er, g_er);
    cudaGetSymbolAddress((void**)&pAh, g_fAh);
    cudaGetSymbolAddress((void**)&pAl, g_fAl);
    cudaGetSymbolAddress((void**)&pBh, g_fBh);
    cudaGetSymbolAddress((void**)&pBl, g_fBl);
    float* el0 = p_el;                   float* er0 = p_er;
    float* el1 = p_el + N_NODES * HEADS; float* er1 = p_er + N_NODES * HEADS;

    cudaFuncSetAttribute((const void*)gemm_proj, cudaFuncAttributeMaxDynamicSharedMemorySize, SM_TOTAL);
    cudaFuncSetAttribute((const void*)k_mlp,     cudaFuncAttributeMaxDynamicSharedMemorySize, MM_TOTAL);

    k_conv_w<<<dim3(6, 6), 256>>>(W1, W2, lw1, lw2, lw3, lw4);
    k_conv_a<<<MTILES + CNT_BLKS, 256>>>(in_feat, dst, N_NODES);
    k_scan<<<1, 1024>>>();
    gemm_proj<<<dim3(MTILES + SCT_X, 6), 256, SM_TOTAL>>>(pAh, pAl, 0, al1, ar1,
                                                          el0, er0, src, dst, p_h, N_NODES);
    k_gather<<<(N_NODES * 32 + 255) / 256, 256>>>(el0, er0, el1, er1, b1, pBh, pBl);
    gemm_proj<<<dim3(MTILES, 6), 256, SM_TOTAL>>>(pBh, pBl, 6, al2, ar2,
                                                  el1, er1, nullptr, nullptr, p_h, N_NODES);
    k_gather<<<(N_NODES * 32 + 255) / 256, 256>>>(el1, er1, nullptr, nullptr, b2, pAh, pAl);
    k_mlp<<<(N_NODES + 63) / 64, 256, MM_TOTAL>>>(pAh, pAl, lb1, lb2, lb3, lb4, lw5, lb5,
                                                  (float*)d_out, N_NODES);
}